// round 1
// baseline (speedup 1.0000x reference)
#include <cuda_runtime.h>
#include <cstdint>

// Problem constants (fixed shapes per reference)
#define Bn 16
#define Sn 4096
#define Dn 128
#define Ln 32            // timesteps per chunk
#define NCn (Sn / Ln)    // 128 chunks per batch

// -------- scratch (device globals; no allocation allowed) --------
__device__ float g_m [Bn * Sn];          // per-t mean(decay)
__device__ float g_s [Bn * Sn];          // per-t sum(exp(c))
__device__ float g_P [Bn * NCn * Dn];    // chunk decay product per channel
__device__ float g_Q [Bn * NCn * Dn];    // chunk additive term per channel
__device__ float g_AM[Bn * NCn];         // chunk product of m
__device__ float g_AS[Bn * NCn];         // chunk additive term for a
__device__ float g_a0[Bn * NCn];         // a at chunk start (exclusive scan)
__device__ float g_b0[Bn * NCn * Dn];    // bst at chunk start (exclusive scan)

__device__ __forceinline__ float fsig(float x) {
    return __fdividef(1.0f, 1.0f + __expf(-x));
}

__device__ __forceinline__ void warp_allreduce2(float& x, float& y) {
#pragma unroll
    for (int off = 16; off; off >>= 1) {
        x += __shfl_xor_sync(0xffffffffu, x, off);
        y += __shfl_xor_sync(0xffffffffu, y, off);
    }
}

// ============================================================================
// Pass A: per-chunk aggregates. One warp per (batch, chunk); lane owns 4 ch.
// ============================================================================
__global__ void __launch_bounds__(128)
passA_kernel(const float* __restrict__ C, const float* __restrict__ V,
             const float* __restrict__ W, const float* __restrict__ enc,
             const float* __restrict__ tmod, const float* __restrict__ cmod) {
    const int warp = (blockIdx.x * blockDim.x + threadIdx.x) >> 5;
    const int lane = threadIdx.x & 31;
    const int b = warp / NCn;
    const int k = warp % NCn;
    const int t0 = k * Ln;
    const int d4 = lane * 4;

    const float4 tm = *reinterpret_cast<const float4*>(tmod + d4);
    const float4 cm = *reinterpret_cast<const float4*>(cmod + d4);
    const float4 eb = *reinterpret_cast<const float4*>(enc + b * Dn + d4);
    float ctx0 = fsig(eb.x * cm.x) * eb.x;
    float ctx1 = fsig(eb.y * cm.y) * eb.y;
    float ctx2 = fsig(eb.z * cm.z) * eb.z;
    float ctx3 = fsig(eb.w * cm.w) * eb.w;

    const size_t base = ((size_t)b * Sn + t0) * Dn + d4;
    const float4* pC = reinterpret_cast<const float4*>(C + base);
    const float4* pV = reinterpret_cast<const float4*>(V + base);
    const float4* pW = reinterpret_cast<const float4*>(W + base);

    float P0 = 1.f, P1 = 1.f, P2 = 1.f, P3 = 1.f;
    float Q0 = 0.f, Q1 = 0.f, Q2 = 0.f, Q3 = 0.f;
    float AM = 1.f, AS = 0.f;

#pragma unroll 4
    for (int t = 0; t < Ln; ++t) {
        const float4 c = pC[t * (Dn / 4)];
        const float4 v = pV[t * (Dn / 4)];
        const float4 w = pW[t * (Dn / 4)];

        const float dd0 = fsig(w.x * tm.x), dd1 = fsig(w.y * tm.y);
        const float dd2 = fsig(w.z * tm.z), dd3 = fsig(w.w * tm.w);
        const float e0 = __expf(c.x), e1 = __expf(c.y);
        const float e2 = __expf(c.z), e3 = __expf(c.w);

        float ds = (dd0 + dd1) + (dd2 + dd3);
        float es = (e0 + e1) + (e2 + e3);
        warp_allreduce2(ds, es);
        const float m = ds * (1.0f / (float)Dn);
        if (lane == 0) {
            g_m[b * Sn + t0 + t] = m;
            g_s[b * Sn + t0 + t] = es;
        }
        AS = fmaf(m, AS, es);
        AM *= m;

        Q0 = fmaf(dd0, Q0, fmaf(e0, v.x, ctx0));
        Q1 = fmaf(dd1, Q1, fmaf(e1, v.y, ctx1));
        Q2 = fmaf(dd2, Q2, fmaf(e2, v.z, ctx2));
        Q3 = fmaf(dd3, Q3, fmaf(e3, v.w, ctx3));
        P0 *= dd0; P1 *= dd1; P2 *= dd2; P3 *= dd3;
    }

    const int agg = (b * NCn + k) * Dn + d4;
    *reinterpret_cast<float4*>(&g_P[agg]) = make_float4(P0, P1, P2, P3);
    *reinterpret_cast<float4*>(&g_Q[agg]) = make_float4(Q0, Q1, Q2, Q3);
    if (lane == 0) {
        g_AM[b * NCn + k] = AM;
        g_AS[b * NCn + k] = AS;
    }
}

// ============================================================================
// Pass B: serial combine over chunks (exclusive scan). One block per batch.
// P/Q staged through shared so loads fly in parallel; scan chain is FMA-only.
// ============================================================================
__global__ void __launch_bounds__(128)
passB_kernel() {
    const int b = blockIdx.x;
    const int d = threadIdx.x;

    __shared__ float sP[32][Dn];
    __shared__ float sQ[32][Dn];
    __shared__ float sAM[NCn];
    __shared__ float sAS[NCn];

    // stage scalar aggregates (NCn == Dn == 128 threads)
    sAM[d] = g_AM[b * NCn + d];
    sAS[d] = g_AS[b * NCn + d];
    __syncthreads();

    // scalar a-scan: all threads compute redundantly; thread 0 stores
    {
        float a = 0.f;
#pragma unroll 8
        for (int k = 0; k < NCn; ++k) {
            if (d == 0) g_a0[b * NCn + k] = a;
            a = fmaf(sAM[k], a, sAS[k]);
        }
    }

    float b0 = 0.f;
    for (int st = 0; st < NCn / 32; ++st) {
        __syncthreads();
#pragma unroll
        for (int kk = 0; kk < 32; ++kk) {
            const int k = st * 32 + kk;
            sP[kk][d] = g_P[(b * NCn + k) * Dn + d];
            sQ[kk][d] = g_Q[(b * NCn + k) * Dn + d];
        }
        __syncthreads();
#pragma unroll
        for (int kk = 0; kk < 32; ++kk) {
            const int k = st * 32 + kk;
            g_b0[(b * NCn + k) * Dn + d] = b0;
            b0 = fmaf(sP[kk][d], b0, sQ[kk][d]);
        }
    }
}

// ============================================================================
// Pass C: replay each chunk from its start state, emit LayerNorm'd output.
// One warp per (batch, chunk); lane owns 4 channels.
// ============================================================================
__global__ void __launch_bounds__(128)
passC_kernel(const float* __restrict__ C, const float* __restrict__ V,
             const float* __restrict__ W, const float* __restrict__ enc,
             const float* __restrict__ tmod, const float* __restrict__ cmod,
             const float* __restrict__ lnw, const float* __restrict__ lnb,
             float* __restrict__ out) {
    const int warpIn = threadIdx.x >> 5;
    const int warp = (blockIdx.x * blockDim.x + threadIdx.x) >> 5;
    const int lane = threadIdx.x & 31;
    const int b = warp / NCn;
    const int k = warp % NCn;
    const int t0 = k * Ln;
    const int d4 = lane * 4;

    __shared__ float sm[4][Ln];
    __shared__ float ss[4][Ln];
    sm[warpIn][lane] = g_m[b * Sn + t0 + lane];  // Ln == 32 == warp size
    ss[warpIn][lane] = g_s[b * Sn + t0 + lane];
    __syncwarp();

    const float4 tm = *reinterpret_cast<const float4*>(tmod + d4);
    const float4 cm = *reinterpret_cast<const float4*>(cmod + d4);
    const float4 eb = *reinterpret_cast<const float4*>(enc + b * Dn + d4);
    const float ctx0 = fsig(eb.x * cm.x) * eb.x;
    const float ctx1 = fsig(eb.y * cm.y) * eb.y;
    const float ctx2 = fsig(eb.z * cm.z) * eb.z;
    const float ctx3 = fsig(eb.w * cm.w) * eb.w;
    const float4 w4 = *reinterpret_cast<const float4*>(lnw + d4);
    const float4 b4 = *reinterpret_cast<const float4*>(lnb + d4);

    float a = g_a0[b * NCn + k];
    float4 bst = *reinterpret_cast<const float4*>(&g_b0[(b * NCn + k) * Dn + d4]);

    const size_t base = ((size_t)b * Sn + t0) * Dn + d4;
    const float4* pC = reinterpret_cast<const float4*>(C + base);
    const float4* pV = reinterpret_cast<const float4*>(V + base);
    const float4* pW = reinterpret_cast<const float4*>(W + base);
    float4* pO = reinterpret_cast<float4*>(out + base);

#pragma unroll 4
    for (int t = 0; t < Ln; ++t) {
        const float4 c = pC[t * (Dn / 4)];
        const float4 v = pV[t * (Dn / 4)];
        const float4 w = pW[t * (Dn / 4)];

        const float dd0 = fsig(w.x * tm.x), dd1 = fsig(w.y * tm.y);
        const float dd2 = fsig(w.z * tm.z), dd3 = fsig(w.w * tm.w);
        const float e0 = __expf(c.x), e1 = __expf(c.y);
        const float e2 = __expf(c.z), e3 = __expf(c.w);

        a = fmaf(sm[warpIn][t], a, ss[warpIn][t]);

        bst.x = fmaf(dd0, bst.x, fmaf(e0, v.x, ctx0));
        bst.y = fmaf(dd1, bst.y, fmaf(e1, v.y, ctx1));
        bst.z = fmaf(dd2, bst.z, fmaf(e2, v.z, ctx2));
        bst.w = fmaf(dd3, bst.w, fmaf(e3, v.w, ctx3));

        const float rinv = __fdividef(1.0f, a + 1e-8f);
        const float o0 = bst.x * rinv, o1 = bst.y * rinv;
        const float o2 = bst.z * rinv, o3 = bst.w * rinv;

        float lsum = (o0 + o1) + (o2 + o3);
        float lsq  = fmaf(o0, o0, fmaf(o1, o1, fmaf(o2, o2, o3 * o3)));
        warp_allreduce2(lsum, lsq);
        const float mu  = lsum * (1.0f / (float)Dn);
        const float var = fmaf(-mu, mu, lsq * (1.0f / (float)Dn));
        const float rstd = rsqrtf(var + 1e-5f);

        float4 r;
        r.x = fmaf((o0 - mu) * rstd, w4.x, b4.x);
        r.y = fmaf((o1 - mu) * rstd, w4.y, b4.y);
        r.z = fmaf((o2 - mu) * rstd, w4.z, b4.z);
        r.w = fmaf((o3 - mu) * rstd, w4.w, b4.w);
        pO[t * (Dn / 4)] = r;
    }
}

// ============================================================================
extern "C" void kernel_launch(void* const* d_in, const int* in_sizes, int n_in,
                              void* d_out, int out_size) {
    (void)in_sizes; (void)n_in; (void)out_size;
    const float* C    = (const float*)d_in[0];
    const float* V    = (const float*)d_in[1];
    const float* W    = (const float*)d_in[2];
    const float* enc  = (const float*)d_in[3];
    const float* tmod = (const float*)d_in[4];
    const float* cmod = (const float*)d_in[5];
    const float* lnw  = (const float*)d_in[6];
    const float* lnb  = (const float*)d_in[7];
    float* out = (float*)d_out;

    const int warpsTotal = Bn * NCn;          // 2048
    const int blocks = warpsTotal / 4;        // 512 blocks of 128 threads

    passA_kernel<<<blocks, 128>>>(C, V, W, enc, tmod, cmod);
    passB_kernel<<<Bn, 128>>>();
    passC_kernel<<<blocks, 128>>>(C, V, W, enc, tmod, cmod, lnw, lnb, out);
}